// round 1
// baseline (speedup 1.0000x reference)
#include <cuda_runtime.h>
#include <math.h>

#define B 4096
#define T 200
#define D 128
#define U 128

// ---------------- device scratch (static globals; no allocations) ----------------
__device__ __align__(128) float g_att[(size_t)T * B];              // [t][b]
__device__ __align__(128) float g_xproj[(size_t)T * B * 384];      // [t][b][384] = x@ [Wu_x|Wr_x|Wc_x]
__device__ int g_perm[B];
__device__ int g_cnt[256];
__device__ int g_off[256];

__device__ __forceinline__ float sigmoidf_(float x) { return 1.0f / (1.0f + __expf(-x)); }
// BN at inference: 1/sqrt(1+1e-9) rounds to exactly 1.0f in fp32, so x_norm == x.
__device__ __forceinline__ float dicef(float x, float alpha) {
    float p = sigmoidf_(x);
    return p * x + alpha * (1.0f - p) * x;
}

// ---------------- counting sort of batch rows by seq_length ----------------
__global__ void k_zero() {
    int i = threadIdx.x;
    if (i < 256) { g_cnt[i] = 0; g_off[i] = 0; }
}
__global__ void k_hist(const int* __restrict__ slen) {
    int b = blockIdx.x * blockDim.x + threadIdx.x;
    if (b < B) {
        int L = slen[b]; L = min(max(L, 0), T);
        atomicAdd(&g_cnt[L], 1);
    }
}
__global__ void k_scanbins() {
    if (threadIdx.x == 0) {
        int acc = 0;
        for (int i = 0; i <= T; i++) { g_off[i] = acc; acc += g_cnt[i]; }
    }
}
__global__ void k_scatter(const int* __restrict__ slen) {
    int b = blockIdx.x * blockDim.x + threadIdx.x;
    if (b < B) {
        int L = slen[b]; L = min(max(L, 0), T);
        int pos = atomicAdd(&g_off[L], 1);
        g_perm[pos] = b;
    }
}

// ---------------- attention: one block per batch row ----------------
// pre1[t][j] = qproj[j] + sum_d k[t][d] * Wtilde[d][j]
// Wtilde[d][j] = (W1[128+d][j] - W1[256+d][j]) + q[d]*W1[384+d][j]
// qproj[j]    = sum_d q[d] * (W1[d][j] + W1[256+d][j])
__global__ __launch_bounds__(256) void k_att(
    const float* __restrict__ x, const float* __restrict__ q_all,
    const int* __restrict__ slen,
    const float* __restrict__ W1, const float* __restrict__ a1,
    const float* __restrict__ W2, const float* __restrict__ a2,
    const float* __restrict__ W3)
{
    __shared__ float qs[D];
    __shared__ float Wt[D * 64];
    __shared__ float qproj[64];
    __shared__ float W2s[64 * 16];
    __shared__ float W3s[16];
    __shared__ float a1s[64];
    __shared__ float a2s[16];
    __shared__ float ks[8][D];
    __shared__ float h1s[8][64];

    int b = blockIdx.x;
    int tid = threadIdx.x;
    int L = slen[b]; L = min(max(L, 0), T);

    if (tid < D) qs[tid] = q_all[(size_t)b * D + tid];
    if (tid < 64) a1s[tid] = a1[tid];
    if (tid < 16) { a2s[tid] = a2[tid]; W3s[tid] = W3[tid]; }
    for (int e = tid; e < 64 * 16; e += 256) W2s[e] = W2[e];
    __syncthreads();

    for (int e = tid; e < D * 64; e += 256) {
        int d = e >> 6, j = e & 63;
        Wt[e] = W1[(128 + d) * 64 + j] - W1[(256 + d) * 64 + j] + qs[d] * W1[(384 + d) * 64 + j];
    }
    if (tid < 64) {
        float acc = 0.0f;
        for (int d = 0; d < D; d++)
            acc += qs[d] * (W1[d * 64 + tid] + W1[(256 + d) * 64 + tid]);
        qproj[tid] = acc;
    }
    __syncthreads();
    if (L == 0) return;

    int w = tid >> 5, lane = tid & 31;
    for (int t0 = 0; t0 < L; t0 += 8) {
        for (int e = tid; e < 8 * D; e += 256) {
            int i = e >> 7, d = e & 127;
            int t = t0 + i;
            if (t < L) ks[i][d] = x[((size_t)b * T + t) * D + d];
        }
        __syncthreads();

        int t = t0 + w;
        if (t < L) {
            float acc0 = qproj[lane], acc1 = qproj[lane + 32];
            #pragma unroll 4
            for (int d = 0; d < D; d++) {
                float kd = ks[w][d];
                acc0 += kd * Wt[d * 64 + lane];
                acc1 += kd * Wt[d * 64 + lane + 32];
            }
            h1s[w][lane]      = dicef(acc0, a1s[lane]);
            h1s[w][lane + 32] = dicef(acc1, a1s[lane + 32]);
            __syncwarp();

            float v = 0.0f;
            if (lane < 16) {
                float acc = 0.0f;
                #pragma unroll 4
                for (int j = 0; j < 64; j++) acc += h1s[w][j] * W2s[j * 16 + lane];
                v = dicef(acc, a2s[lane]) * W3s[lane];
            }
            #pragma unroll
            for (int off = 16; off > 0; off >>= 1) v += __shfl_xor_sync(0xffffffffu, v, off);
            if (lane == 0) g_att[(size_t)t * B + b] = sigmoidf_(v);
        }
        __syncthreads();
    }
}

// ---------------- x projections: one block per batch row ----------------
// g_xproj[t][b][j] = sum_d x[b][t][d] * Wx[d][j], Wx = [Wu[0:128] | Wr[0:128] | Wc[0:128]]
__global__ __launch_bounds__(256) void k_xproj(
    const float* __restrict__ x, const int* __restrict__ slen,
    const float* __restrict__ Wu, const float* __restrict__ Wr, const float* __restrict__ Wc)
{
    extern __shared__ float Ws[];   // [128][384]
    __shared__ float xs[4][D];

    int b = blockIdx.x;
    int tid = threadIdx.x;
    int L = slen[b]; L = min(max(L, 0), T);
    if (L == 0) return;

    for (int e = tid; e < D * 384; e += 256) {
        int d = e / 384, j = e % 384;
        float v;
        if (j < 128)      v = Wu[d * 128 + j];
        else if (j < 256) v = Wr[d * 128 + (j - 128)];
        else              v = Wc[d * 128 + (j - 256)];
        Ws[e] = v;
    }
    __syncthreads();

    int tg = tid >> 6;      // 0..3  (uniform within each warp)
    int jg = tid & 63;      // 0..63
    int j0 = jg * 6;        // 6 output cols per thread (64*6 = 384)

    for (int t0 = 0; t0 < L; t0 += 4) {
        for (int e = tid; e < 4 * D; e += 256) {
            int i = e >> 7, d = e & 127;
            int t = t0 + i;
            if (t < L) xs[i][d] = x[((size_t)b * T + t) * D + d];
        }
        __syncthreads();

        int t = t0 + tg;
        if (t < L) {
            float acc[6] = {0, 0, 0, 0, 0, 0};
            #pragma unroll 2
            for (int d = 0; d < D; d++) {
                float xd = xs[tg][d];
                const float* wp = &Ws[d * 384 + j0];
                float2 w01 = *(const float2*)(wp);
                float2 w23 = *(const float2*)(wp + 2);
                float2 w45 = *(const float2*)(wp + 4);
                acc[0] += xd * w01.x; acc[1] += xd * w01.y;
                acc[2] += xd * w23.x; acc[3] += xd * w23.y;
                acc[4] += xd * w45.x; acc[5] += xd * w45.y;
            }
            size_t base = ((size_t)t * B + b) * 384 + j0;
            #pragma unroll
            for (int m = 0; m < 6; m++) g_xproj[base + m] = acc[m];
        }
        __syncthreads();
    }
}

// ---------------- AUGRU scan: persistent, 32 sorted rows per block ----------------
__global__ __launch_bounds__(256) void k_augru(
    const int* __restrict__ slen,
    const float* __restrict__ Wu, const float* __restrict__ Wr, const float* __restrict__ Wc,
    float* __restrict__ out)
{
    extern __shared__ float sm[];
    float* Wus = sm;                 // 16384 : Wu rows 128..255 ([d][u])
    float* Wrs = sm + 16384;
    float* Wcs = sm + 32768;
    float* hT  = sm + 49152;         // [128][32]  h transposed
    float* rhT = sm + 53248;         // [128][32]  (r*h) transposed
    __shared__ int   Ls[32];
    __shared__ int   bi[32];
    __shared__ float atts[32];
    __shared__ int   LmaxS;

    int tid = threadIdx.x;
    for (int e = tid; e < 16384; e += 256) {
        Wus[e] = Wu[16384 + e];
        Wrs[e] = Wr[16384 + e];
        Wcs[e] = Wc[16384 + e];
    }
    for (int e = tid; e < 4096; e += 256) hT[e] = 0.0f;
    if (tid < 32) {
        int b = g_perm[blockIdx.x * 32 + tid];
        bi[tid] = b;
        int L = slen[b]; L = min(max(L, 0), T);
        Ls[tid] = L;
    }
    __syncthreads();
    if (tid == 0) {
        int m = 0;
        for (int i = 0; i < 32; i++) m = max(m, Ls[i]);
        LmaxS = m;
    }
    __syncthreads();
    int Lmax = LmaxS;

    int w = tid >> 5, lane = tid & 31;
    int r0 = w * 4;        // 4 rows per warp (8 warps -> 32 rows)
    int c0 = lane * 4;     // 4 cols per lane (32 lanes -> 128 cols)

    for (int t = 0; t < Lmax; t++) {
        if (tid < 32) atts[tid] = g_att[(size_t)t * B + bi[tid]];

        float accU[4][4], accR[4][4];
        #pragma unroll
        for (int i = 0; i < 4; i++)
            #pragma unroll
            for (int j = 0; j < 4; j++) { accU[i][j] = 0.0f; accR[i][j] = 0.0f; }

        #pragma unroll 2
        for (int d = 0; d < 128; d++) {
            float4 hv = *(const float4*)&hT[d * 32 + r0];      // broadcast within warp
            float4 wu = *(const float4*)&Wus[d * 128 + c0];    // conflict-free
            float4 wr = *(const float4*)&Wrs[d * 128 + c0];
            float hvv[4] = {hv.x, hv.y, hv.z, hv.w};
            float wuv[4] = {wu.x, wu.y, wu.z, wu.w};
            float wrv[4] = {wr.x, wr.y, wr.z, wr.w};
            #pragma unroll
            for (int i = 0; i < 4; i++)
                #pragma unroll
                for (int j = 0; j < 4; j++) {
                    accU[i][j] += hvv[i] * wuv[j];
                    accR[i][j] += hvv[i] * wrv[j];
                }
        }

        float uu[4][4];
        #pragma unroll
        for (int i = 0; i < 4; i++) {
            int brow = bi[r0 + i];
            size_t base = ((size_t)t * B + brow) * 384;
            float4 xu = *(const float4*)&g_xproj[base + c0];
            float4 xr = *(const float4*)&g_xproj[base + 128 + c0];
            float xuv[4] = {xu.x, xu.y, xu.z, xu.w};
            float xrv[4] = {xr.x, xr.y, xr.z, xr.w};
            #pragma unroll
            for (int j = 0; j < 4; j++) {
                uu[i][j] = sigmoidf_(accU[i][j] + xuv[j]);
                float rr = sigmoidf_(accR[i][j] + xrv[j]);
                int idx = (c0 + j) * 32 + r0 + i;
                rhT[idx] = rr * hT[idx];
            }
        }
        __syncthreads();   // rhT ready

        float accC[4][4];
        #pragma unroll
        for (int i = 0; i < 4; i++)
            #pragma unroll
            for (int j = 0; j < 4; j++) accC[i][j] = 0.0f;

        #pragma unroll 2
        for (int d = 0; d < 128; d++) {
            float4 hv = *(const float4*)&rhT[d * 32 + r0];
            float4 wc = *(const float4*)&Wcs[d * 128 + c0];
            float hvv[4] = {hv.x, hv.y, hv.z, hv.w};
            float wcv[4] = {wc.x, wc.y, wc.z, wc.w};
            #pragma unroll
            for (int i = 0; i < 4; i++)
                #pragma unroll
                for (int j = 0; j < 4; j++)
                    accC[i][j] += hvv[i] * wcv[j];
        }

        #pragma unroll
        for (int i = 0; i < 4; i++) {
            int row = r0 + i;
            if (t < Ls[row]) {
                int brow = bi[row];
                float a = atts[row];
                size_t base = ((size_t)t * B + brow) * 384 + 256;
                float4 xc = *(const float4*)&g_xproj[base + c0];
                float xcv[4] = {xc.x, xc.y, xc.z, xc.w};
                #pragma unroll
                for (int j = 0; j < 4; j++) {
                    float cval = tanhf(accC[i][j] + xcv[j]);
                    float ut = uu[i][j] * a;
                    int idx = (c0 + j) * 32 + row;
                    float hold = hT[idx];
                    hT[idx] = hold + ut * (cval - hold);
                }
            }
        }
        __syncthreads();   // hT (and atts) safe for next iteration
    }

    for (int e = tid; e < 32 * 128; e += 256) {
        int i = e >> 7, u = e & 127;
        out[(size_t)bi[i] * U + u] = hT[u * 32 + i];
    }
}

// ---------------- launch ----------------
extern "C" void kernel_launch(void* const* d_in, const int* in_sizes, int n_in,
                              void* d_out, int out_size)
{
    const float* x    = (const float*)d_in[0];   // [B,T,D]
    const float* q    = (const float*)d_in[1];   // [B,D]
    const int*   slen = (const int*)d_in[2];     // [B,1]
    const float* W1   = (const float*)d_in[3];   // [512,64]
    const float* a1   = (const float*)d_in[4];   // [64]
    const float* W2   = (const float*)d_in[5];   // [64,16]
    const float* a2   = (const float*)d_in[6];   // [16]
    const float* W3   = (const float*)d_in[7];   // [16,1]
    const float* Wu   = (const float*)d_in[8];   // [256,128]
    const float* Wr   = (const float*)d_in[9];   // [256,128]
    const float* Wc   = (const float*)d_in[10];  // [256,128]
    float* out = (float*)d_out;

    // idempotent; safe to call every launch (not a stream op, no allocation)
    cudaFuncSetAttribute(k_xproj, cudaFuncAttributeMaxDynamicSharedMemorySize, 128 * 384 * 4);
    cudaFuncSetAttribute(k_augru, cudaFuncAttributeMaxDynamicSharedMemorySize, 57344 * 4);

    k_zero<<<1, 256>>>();
    k_hist<<<B / 256, 256>>>(slen);
    k_scanbins<<<1, 32>>>();
    k_scatter<<<B / 256, 256>>>(slen);

    k_att<<<B, 256>>>(x, q, slen, W1, a1, W2, a2, W3);
    k_xproj<<<B, 256, 128 * 384 * 4>>>(x, slen, Wu, Wr, Wc);
    k_augru<<<B / 32, 256, 57344 * 4>>>(slen, Wu, Wr, Wc, out);
}

// round 2
// speedup vs baseline: 2.4096x; 2.4096x over previous
#include <cuda_runtime.h>
#include <math.h>

#define B 4096
#define T 200
#define D 128
#define U 128

// ---------------- device scratch (static globals; no allocations) ----------------
__device__ __align__(128) float g_att[(size_t)T * B];              // [t][b]
__device__ __align__(128) float g_xproj[(size_t)T * B * 384];      // [t][b][384]
__device__ int g_perm[B];
__device__ int g_cnt[256];
__device__ int g_off[256];

__device__ __forceinline__ float sigmoidf_(float x) { return 1.0f / (1.0f + __expf(-x)); }
__device__ __forceinline__ float tanhf_(float x) { return 1.0f - 2.0f / (1.0f + __expf(2.0f * x)); }
__device__ __forceinline__ float dicef(float x, float alpha) {
    float p = sigmoidf_(x);
    return p * x + alpha * (1.0f - p) * x;
}
__device__ __forceinline__ unsigned f2tf32(float x) {
    unsigned r; asm("cvt.rna.tf32.f32 %0, %1;" : "=r"(r) : "f"(x)); return r;
}
__device__ __forceinline__ void mma_tf32(float c[4], const unsigned a[4], const unsigned b[2]) {
    asm("mma.sync.aligned.m16n8k8.row.col.f32.tf32.tf32.f32 "
        "{%0,%1,%2,%3}, {%4,%5,%6,%7}, {%8,%9}, {%0,%1,%2,%3};\n"
        : "+f"(c[0]), "+f"(c[1]), "+f"(c[2]), "+f"(c[3])
        : "r"(a[0]), "r"(a[1]), "r"(a[2]), "r"(a[3]), "r"(b[0]), "r"(b[1]));
}

// ---------------- counting sort of batch rows by seq_length ----------------
__global__ void k_zero() {
    int i = threadIdx.x;
    if (i < 256) { g_cnt[i] = 0; g_off[i] = 0; }
}
__global__ void k_hist(const int* __restrict__ slen) {
    int b = blockIdx.x * blockDim.x + threadIdx.x;
    if (b < B) { int L = slen[b]; L = min(max(L, 0), T); atomicAdd(&g_cnt[L], 1); }
}
__global__ void k_scanbins() {
    if (threadIdx.x == 0) {
        int acc = 0;
        for (int i = 0; i <= T; i++) { g_off[i] = acc; acc += g_cnt[i]; }
    }
}
__global__ void k_scatter(const int* __restrict__ slen) {
    int b = blockIdx.x * blockDim.x + threadIdx.x;
    if (b < B) {
        int L = slen[b]; L = min(max(L, 0), T);
        int pos = atomicAdd(&g_off[L], 1);
        g_perm[pos] = b;
    }
}

// ---------------- attention: one block per batch row (unchanged, SIMT) ----------------
__global__ __launch_bounds__(256) void k_att(
    const float* __restrict__ x, const float* __restrict__ q_all,
    const int* __restrict__ slen,
    const float* __restrict__ W1, const float* __restrict__ a1,
    const float* __restrict__ W2, const float* __restrict__ a2,
    const float* __restrict__ W3)
{
    __shared__ float qs[D];
    __shared__ float Wt[D * 64];
    __shared__ float qproj[64];
    __shared__ float W2s[64 * 16];
    __shared__ float W3s[16];
    __shared__ float a1s[64];
    __shared__ float a2s[16];
    __shared__ float ks[8][D];
    __shared__ float h1s[8][64];

    int b = blockIdx.x;
    int tid = threadIdx.x;
    int L = slen[b]; L = min(max(L, 0), T);

    if (tid < D) qs[tid] = q_all[(size_t)b * D + tid];
    if (tid < 64) a1s[tid] = a1[tid];
    if (tid < 16) { a2s[tid] = a2[tid]; W3s[tid] = W3[tid]; }
    for (int e = tid; e < 64 * 16; e += 256) W2s[e] = W2[e];
    __syncthreads();

    for (int e = tid; e < D * 64; e += 256) {
        int d = e >> 6, j = e & 63;
        Wt[e] = W1[(128 + d) * 64 + j] - W1[(256 + d) * 64 + j] + qs[d] * W1[(384 + d) * 64 + j];
    }
    if (tid < 64) {
        float acc = 0.0f;
        for (int d = 0; d < D; d++)
            acc += qs[d] * (W1[d * 64 + tid] + W1[(256 + d) * 64 + tid]);
        qproj[tid] = acc;
    }
    __syncthreads();
    if (L == 0) return;

    int w = tid >> 5, lane = tid & 31;
    for (int t0 = 0; t0 < L; t0 += 8) {
        for (int e = tid; e < 8 * D; e += 256) {
            int i = e >> 7, d = e & 127;
            int t = t0 + i;
            if (t < L) ks[i][d] = x[((size_t)b * T + t) * D + d];
        }
        __syncthreads();

        int t = t0 + w;
        if (t < L) {
            float acc0 = qproj[lane], acc1 = qproj[lane + 32];
            #pragma unroll 4
            for (int d = 0; d < D; d++) {
                float kd = ks[w][d];
                acc0 += kd * Wt[d * 64 + lane];
                acc1 += kd * Wt[d * 64 + lane + 32];
            }
            h1s[w][lane]      = dicef(acc0, a1s[lane]);
            h1s[w][lane + 32] = dicef(acc1, a1s[lane + 32]);
            __syncwarp();

            float v = 0.0f;
            if (lane < 16) {
                float acc = 0.0f;
                #pragma unroll 4
                for (int j = 0; j < 64; j++) acc += h1s[w][j] * W2s[j * 16 + lane];
                v = dicef(acc, a2s[lane]) * W3s[lane];
            }
            #pragma unroll
            for (int off = 16; off > 0; off >>= 1) v += __shfl_xor_sync(0xffffffffu, v, off);
            if (lane == 0) g_att[(size_t)t * B + b] = sigmoidf_(v);
        }
        __syncthreads();
    }
}

// ---------------- x projections: tf32 MMA GEMM, one block per batch row ----------------
// g_xproj[t][b][0:384] = x[b][t][:] @ [Wu_x | Wr_x | Wc_x]
__global__ __launch_bounds__(256) void k_xproj(
    const float* __restrict__ x, const int* __restrict__ slen,
    const float* __restrict__ Wu, const float* __restrict__ Wr, const float* __restrict__ Wc)
{
    extern __shared__ unsigned smu[];
    unsigned* Ws = smu;            // [128][384] tf32, cols XOR-swizzled by (d&3)<<3
    unsigned* xs = smu + 49152;    // [32][132]  tf32

    int b = blockIdx.x, tid = threadIdx.x;
    int L = slen[b]; L = min(max(L, 0), T);
    if (L == 0) return;

    for (int e = tid; e < 128 * 384; e += 256) {
        int d = e / 384, n = e % 384;
        float v = (n < 128) ? Wu[d * 128 + n] : (n < 256) ? Wr[d * 128 + n - 128] : Wc[d * 128 + n - 256];
        Ws[d * 384 + (n ^ ((d & 3) << 3))] = f2tf32(v);
    }
    __syncthreads();

    const int w = tid >> 5, lane = tid & 31, g = lane >> 2, tig = lane & 3;
    const int n0w = w * 48;

    for (int t0 = 0; t0 < L; t0 += 32) {
        for (int e = tid; e < 32 * 128; e += 256) {
            int r = e >> 7, d = e & 127;
            int t = t0 + r;
            float v = (t < L) ? x[((size_t)b * T + t) * D + d] : 0.0f;
            xs[r * 132 + d] = f2tf32(v);
        }
        __syncthreads();

        float acc[2][6][4];
        #pragma unroll
        for (int mt = 0; mt < 2; mt++)
            #pragma unroll
            for (int nt = 0; nt < 6; nt++)
                #pragma unroll
                for (int k = 0; k < 4; k++) acc[mt][nt][k] = 0.0f;

        #pragma unroll 4
        for (int s = 0; s < 16; s++) {
            int d0 = 8 * s;
            unsigned a[2][4];
            #pragma unroll
            for (int mt = 0; mt < 2; mt++) {
                int r0 = mt * 16 + g;
                a[mt][0] = xs[r0 * 132 + d0 + tig];
                a[mt][1] = xs[(r0 + 8) * 132 + d0 + tig];
                a[mt][2] = xs[r0 * 132 + d0 + tig + 4];
                a[mt][3] = xs[(r0 + 8) * 132 + d0 + tig + 4];
            }
            #pragma unroll
            for (int nt = 0; nt < 6; nt++) {
                int colsw = (n0w + nt * 8 + g) ^ (tig << 3);
                unsigned bb[2];
                bb[0] = Ws[(d0 + tig) * 384 + colsw];
                bb[1] = Ws[(d0 + tig + 4) * 384 + colsw];
                mma_tf32(acc[0][nt], a[0], bb);
                mma_tf32(acc[1][nt], a[1], bb);
            }
        }
        __syncthreads();   // xs consumed; safe to restage next iter

        #pragma unroll
        for (int mt = 0; mt < 2; mt++)
            #pragma unroll
            for (int nt = 0; nt < 6; nt++) {
                int col = n0w + nt * 8 + tig * 2;
                int t1 = t0 + mt * 16 + g;
                if (t1 < L)
                    *(float2*)&g_xproj[((size_t)t1 * B + b) * 384 + col] =
                        make_float2(acc[mt][nt][0], acc[mt][nt][1]);
                int t2 = t1 + 8;
                if (t2 < L)
                    *(float2*)&g_xproj[((size_t)t2 * B + b) * 384 + col] =
                        make_float2(acc[mt][nt][2], acc[mt][nt][3]);
            }
    }
}

// ---------------- AUGRU scan: tf32 MMA, persistent, 32 sorted rows per block ----------------
__global__ __launch_bounds__(256) void k_augru(
    const int* __restrict__ slen,
    const float* __restrict__ Wu, const float* __restrict__ Wr, const float* __restrict__ Wc,
    float* __restrict__ out)
{
    extern __shared__ unsigned smu[];
    unsigned* Wus  = smu;                    // [128][128] tf32, XOR-swizzled
    unsigned* Wrs  = smu + 16384;
    unsigned* Wcs  = smu + 32768;
    unsigned* hTs  = smu + 49152;            // [32][132] tf32 copy of h
    unsigned* rhTs = smu + 49152 + 4224;     // [32][132] tf32 (r*h)
    __shared__ int   Ls[32];
    __shared__ int   bis[32];
    __shared__ float atts[32];
    __shared__ int   LmaxS;

    int tid = threadIdx.x;
    for (int e = tid; e < 16384; e += 256) {
        int d = e >> 7, n = e & 127;
        int sw = d * 128 + (n ^ ((d & 3) << 3));
        Wus[sw] = f2tf32(Wu[16384 + e]);
        Wrs[sw] = f2tf32(Wr[16384 + e]);
        Wcs[sw] = f2tf32(Wc[16384 + e]);
    }
    for (int e = tid; e < 4224; e += 256) hTs[e] = 0u;
    if (tid < 32) {
        int b = g_perm[blockIdx.x * 32 + tid];
        bis[tid] = b;
        int L = slen[b]; L = min(max(L, 0), T);
        Ls[tid] = L;
    }
    __syncthreads();
    if (tid == 0) { int m = 0; for (int i = 0; i < 32; i++) m = max(m, Ls[i]); LmaxS = m; }
    __syncthreads();
    const int Lmax = LmaxS;

    const int w = tid >> 5, lane = tid & 31, g = lane >> 2, tig = lane & 3;
    const int n0w = w * 16;

    int myb[4], myL[4], myrow[4];
    #pragma unroll
    for (int ri = 0; ri < 4; ri++) {
        int row = (ri >> 1) * 16 + (ri & 1) * 8 + g;
        myrow[ri] = row; myb[ri] = bis[row]; myL[ri] = Ls[row];
    }

    float hm[2][2][4];   // fp32 master h; c-frag layout
    #pragma unroll
    for (int mt = 0; mt < 2; mt++)
        #pragma unroll
        for (int nt = 0; nt < 2; nt++)
            #pragma unroll
            for (int k = 0; k < 4; k++) hm[mt][nt][k] = 0.0f;

    for (int t = 0; t < Lmax; t++) {
        // prefetch x-projections for my 16 output elements (3 gates)
        float2 xu[4][2], xr[4][2], xc[4][2];
        #pragma unroll
        for (int ri = 0; ri < 4; ri++) {
            size_t base = ((size_t)t * B + myb[ri]) * 384;
            #pragma unroll
            for (int nt = 0; nt < 2; nt++) {
                int c = n0w + nt * 8 + tig * 2;
                xu[ri][nt] = *(const float2*)&g_xproj[base + c];
                xr[ri][nt] = *(const float2*)&g_xproj[base + 128 + c];
                xc[ri][nt] = *(const float2*)&g_xproj[base + 256 + c];
            }
        }
        if (tid < 32) atts[tid] = g_att[(size_t)t * B + bis[tid]];

        // ---- U and R GEMMs: h @ Wu_h, h @ Wr_h ----
        float accU[2][2][4], accR[2][2][4];
        #pragma unroll
        for (int mt = 0; mt < 2; mt++)
            #pragma unroll
            for (int nt = 0; nt < 2; nt++)
                #pragma unroll
                for (int k = 0; k < 4; k++) { accU[mt][nt][k] = 0.0f; accR[mt][nt][k] = 0.0f; }

        #pragma unroll 4
        for (int s = 0; s < 16; s++) {
            int d0 = 8 * s;
            unsigned a[2][4];
            #pragma unroll
            for (int mt = 0; mt < 2; mt++) {
                int r0 = mt * 16 + g;
                a[mt][0] = hTs[r0 * 132 + d0 + tig];
                a[mt][1] = hTs[(r0 + 8) * 132 + d0 + tig];
                a[mt][2] = hTs[r0 * 132 + d0 + tig + 4];
                a[mt][3] = hTs[(r0 + 8) * 132 + d0 + tig + 4];
            }
            #pragma unroll
            for (int nt = 0; nt < 2; nt++) {
                int colsw = (n0w + nt * 8 + g) ^ (tig << 3);
                unsigned bu[2], br[2];
                bu[0] = Wus[(d0 + tig) * 128 + colsw];
                bu[1] = Wus[(d0 + tig + 4) * 128 + colsw];
                br[0] = Wrs[(d0 + tig) * 128 + colsw];
                br[1] = Wrs[(d0 + tig + 4) * 128 + colsw];
                #pragma unroll
                for (int mt = 0; mt < 2; mt++) {
                    mma_tf32(accU[mt][nt], a[mt], bu);
                    mma_tf32(accR[mt][nt], a[mt], br);
                }
            }
        }

        // gates; store r*h (tf32) for the C GEMM
        float uu[2][2][4];
        #pragma unroll
        for (int mt = 0; mt < 2; mt++)
            #pragma unroll
            for (int nt = 0; nt < 2; nt++) {
                int col = n0w + nt * 8 + tig * 2;
                #pragma unroll
                for (int half = 0; half < 2; half++) {
                    int ri = mt * 2 + half;
                    int row = myrow[ri];
                    float u0 = sigmoidf_(accU[mt][nt][half * 2 + 0] + xu[ri][nt].x);
                    float u1 = sigmoidf_(accU[mt][nt][half * 2 + 1] + xu[ri][nt].y);
                    float r0 = sigmoidf_(accR[mt][nt][half * 2 + 0] + xr[ri][nt].x);
                    float r1 = sigmoidf_(accR[mt][nt][half * 2 + 1] + xr[ri][nt].y);
                    uu[mt][nt][half * 2 + 0] = u0;
                    uu[mt][nt][half * 2 + 1] = u1;
                    rhTs[row * 132 + col]     = f2tf32(r0 * hm[mt][nt][half * 2 + 0]);
                    rhTs[row * 132 + col + 1] = f2tf32(r1 * hm[mt][nt][half * 2 + 1]);
                }
            }
        __syncthreads();   // rhTs ready (and atts visible)

        // ---- C GEMM: (r*h) @ Wc_h ----
        float accC[2][2][4];
        #pragma unroll
        for (int mt = 0; mt < 2; mt++)
            #pragma unroll
            for (int nt = 0; nt < 2; nt++)
                #pragma unroll
                for (int k = 0; k < 4; k++) accC[mt][nt][k] = 0.0f;

        #pragma unroll 4
        for (int s = 0; s < 16; s++) {
            int d0 = 8 * s;
            unsigned a[2][4];
            #pragma unroll
            for (int mt = 0; mt < 2; mt++) {
                int r0 = mt * 16 + g;
                a[mt][0] = rhTs[r0 * 132 + d0 + tig];
                a[mt][1] = rhTs[(r0 + 8) * 132 + d0 + tig];
                a[mt][2] = rhTs[r0 * 132 + d0 + tig + 4];
                a[mt][3] = rhTs[(r0 + 8) * 132 + d0 + tig + 4];
            }
            #pragma unroll
            for (int nt = 0; nt < 2; nt++) {
                int colsw = (n0w + nt * 8 + g) ^ (tig << 3);
                unsigned bc[2];
                bc[0] = Wcs[(d0 + tig) * 128 + colsw];
                bc[1] = Wcs[(d0 + tig + 4) * 128 + colsw];
                #pragma unroll
                for (int mt = 0; mt < 2; mt++)
                    mma_tf32(accC[mt][nt], a[mt], bc);
            }
        }

        // update h (fp32 master), refresh tf32 copy
        #pragma unroll
        for (int mt = 0; mt < 2; mt++)
            #pragma unroll
            for (int nt = 0; nt < 2; nt++) {
                int col = n0w + nt * 8 + tig * 2;
                #pragma unroll
                for (int half = 0; half < 2; half++) {
                    int ri = mt * 2 + half;
                    int row = myrow[ri];
                    if (t < myL[ri]) {
                        float a_att = atts[row];
                        float c0 = tanhf_(accC[mt][nt][half * 2 + 0] + xc[ri][nt].x);
                        float c1 = tanhf_(accC[mt][nt][half * 2 + 1] + xc[ri][nt].y);
                        float ut0 = uu[mt][nt][half * 2 + 0] * a_att;
                        float ut1 = uu[mt][nt][half * 2 + 1] * a_att;
                        hm[mt][nt][half * 2 + 0] += ut0 * (c0 - hm[mt][nt][half * 2 + 0]);
                        hm[mt][nt][half * 2 + 1] += ut1 * (c1 - hm[mt][nt][half * 2 + 1]);
                    }
                    hTs[row * 132 + col]     = f2tf32(hm[mt][nt][half * 2 + 0]);
                    hTs[row * 132 + col + 1] = f2tf32(hm[mt][nt][half * 2 + 1]);
                }
            }
        __syncthreads();   // hTs/rhTs/atts safe for next step
    }

    // write final h
    #pragma unroll
    for (int mt = 0; mt < 2; mt++)
        #pragma unroll
        for (int nt = 0; nt < 2; nt++) {
            int col = n0w + nt * 8 + tig * 2;
            #pragma unroll
            for (int half = 0; half < 2; half++) {
                int ri = mt * 2 + half;
                out[(size_t)myb[ri] * U + col]     = hm[mt][nt][half * 2 + 0];
                out[(size_t)myb[ri] * U + col + 1] = hm[mt][nt][half * 2 + 1];
            }
        }
}

// ---------------- launch ----------------
extern "C" void kernel_launch(void* const* d_in, const int* in_sizes, int n_in,
                              void* d_out, int out_size)
{
    const float* x    = (const float*)d_in[0];   // [B,T,D]
    const float* q    = (const float*)d_in[1];   // [B,D]
    const int*   slen = (const int*)d_in[2];     // [B,1]
    const float* W1   = (const float*)d_in[3];   // [512,64]
    const float* a1   = (const float*)d_in[4];   // [64]
    const float* W2   = (const float*)d_in[5];   // [64,16]
    const float* a2   = (const float*)d_in[6];   // [16]
    const float* W3   = (const float*)d_in[7];   // [16,1]
    const float* Wu   = (const float*)d_in[8];   // [256,128]
    const float* Wr   = (const float*)d_in[9];   // [256,128]
    const float* Wc   = (const float*)d_in[10];  // [256,128]
    float* out = (float*)d_out;

    const int XPROJ_SMEM = (128 * 384 + 32 * 132) * 4;            // 213,504
    const int AUGRU_SMEM = (3 * 16384 + 2 * 32 * 132) * 4;        // 230,400

    cudaFuncSetAttribute(k_xproj, cudaFuncAttributeMaxDynamicSharedMemorySize, XPROJ_SMEM);
    cudaFuncSetAttribute(k_augru, cudaFuncAttributeMaxDynamicSharedMemorySize, AUGRU_SMEM);

    k_zero<<<1, 256>>>();
    k_hist<<<B / 256, 256>>>(slen);
    k_scanbins<<<1, 32>>>();
    k_scatter<<<B / 256, 256>>>(slen);

    k_att<<<B, 256>>>(x, q, slen, W1, a1, W2, a2, W3);
    k_xproj<<<B, 256, XPROJ_SMEM>>>(x, slen, Wu, Wr, Wc);
    k_augru<<<B / 32, 256, AUGRU_SMEM>>>(slen, Wu, Wr, Wc, out);
}

// round 3
// speedup vs baseline: 6.6757x; 2.7705x over previous
#include <cuda_runtime.h>
#include <cuda_fp16.h>
#include <math.h>

#define B 4096
#define T 200
#define D 128
#define U 128

// ---------------- device scratch ----------------
__device__ __align__(128) float g_att[(size_t)T * B];   // [t][b]
__device__ int g_perm[B];

__device__ __forceinline__ float sigmoidf_(float x) { return 1.0f / (1.0f + __expf(-x)); }
__device__ __forceinline__ float tanhf_(float x) { return 1.0f - 2.0f / (1.0f + __expf(2.0f * x)); }
__device__ __forceinline__ float dicef(float x, float alpha) {
    float p = sigmoidf_(x);
    return p * x + alpha * (1.0f - p) * x;
}
__device__ __forceinline__ unsigned packh2(float a, float b) {
    __half2 h = __floats2half2_rn(a, b);
    return *(unsigned*)&h;
}
__device__ __forceinline__ void mma_f16(float c[4], const unsigned a[4], const unsigned b[2]) {
    asm("mma.sync.aligned.m16n8k16.row.col.f32.f16.f16.f32 "
        "{%0,%1,%2,%3}, {%4,%5,%6,%7}, {%8,%9}, {%0,%1,%2,%3};\n"
        : "+f"(c[0]), "+f"(c[1]), "+f"(c[2]), "+f"(c[3])
        : "r"(a[0]), "r"(a[1]), "r"(a[2]), "r"(a[3]), "r"(b[0]), "r"(b[1]));
}

// A-layout (rows x 128 halves = 64 words), word kw swizzled by ((row&7)<<2).
// B-layout identical with row -> output col n.

// ---------------- single-kernel counting sort ----------------
__global__ __launch_bounds__(512) void k_sort(const int* __restrict__ slen) {
    __shared__ int cnt[256];
    __shared__ int off[256];
    int tid = threadIdx.x;
    if (tid < 256) cnt[tid] = 0;
    __syncthreads();
    for (int b = tid; b < B; b += 512) {
        int L = slen[b]; L = min(max(L, 0), T);
        atomicAdd(&cnt[L], 1);
    }
    __syncthreads();
    if (tid == 0) {
        int acc = 0;
        for (int i = 0; i <= T; i++) { off[i] = acc; acc += cnt[i]; }
    }
    __syncthreads();
    for (int b = tid; b < B; b += 512) {
        int L = slen[b]; L = min(max(L, 0), T);
        int pos = atomicAdd(&off[L], 1);
        g_perm[pos] = b;
    }
}

// ---------------- attention: one block per batch row, fp16 MMA layer-1 ----------------
__global__ __launch_bounds__(256) void k_att(
    const float* __restrict__ x, const float* __restrict__ q_all,
    const int* __restrict__ slen,
    const float* __restrict__ W1, const float* __restrict__ a1,
    const float* __restrict__ W2, const float* __restrict__ a2,
    const float* __restrict__ W3)
{
    __shared__ unsigned WtB[64 * 64];   // [n=64][kw=64] fp16x2, swizzled
    __shared__ unsigned xk[32 * 64];    // [row=32][kw=64] fp16x2, swizzled
    __shared__ float h1s[32 * 68];
    __shared__ float W2s[64 * 16];
    __shared__ float qs[D];
    __shared__ float qproj[64];
    __shared__ float a1s[64];
    __shared__ float a2s[16];
    __shared__ float W3s[16];

    int b = blockIdx.x;
    int tid = threadIdx.x;
    int L = slen[b]; L = min(max(L, 0), T);

    if (tid < D) qs[tid] = q_all[(size_t)b * D + tid];
    if (tid < 64) a1s[tid] = a1[tid];
    if (tid < 16) { a2s[tid] = a2[tid]; W3s[tid] = W3[tid]; }
    for (int e = tid; e < 64 * 16; e += 256) W2s[e] = W2[e];
    __syncthreads();

    // Wtilde[d][n] = W1[128+d][n] - W1[256+d][n] + q[d]*W1[384+d][n], fp16 B-layout
    for (int e = tid; e < 64 * 64; e += 256) {
        int n = e & 63, kw = e >> 6;
        int d0 = 2 * kw, d1 = 2 * kw + 1;
        float v0 = W1[(128 + d0) * 64 + n] - W1[(256 + d0) * 64 + n] + qs[d0] * W1[(384 + d0) * 64 + n];
        float v1 = W1[(128 + d1) * 64 + n] - W1[(256 + d1) * 64 + n] + qs[d1] * W1[(384 + d1) * 64 + n];
        WtB[n * 64 + (kw ^ ((n & 7) << 2))] = packh2(v0, v1);
    }
    if (tid < 64) {
        float acc = 0.0f;
        for (int d = 0; d < D; d++)
            acc += qs[d] * (W1[d * 64 + tid] + W1[(256 + d) * 64 + tid]);
        qproj[tid] = acc;
    }
    __syncthreads();
    if (L == 0) return;

    const int w = tid >> 5, lane = tid & 31, g = lane >> 2, tig = lane & 3;
    const int gsw = g << 2;

    for (int t0 = 0; t0 < L; t0 += 32) {
        // stage 32 rows of x as fp16
        {
            int r = tid >> 3, c = tid & 7;
            int rs = (r & 7) << 2;
            int t = t0 + r;
            unsigned wv[8];
            if (t < L) {
                const float4* xp = (const float4*)&x[((size_t)b * T + t) * D + c * 16];
                #pragma unroll
                for (int q4 = 0; q4 < 4; q4++) {
                    float4 v = xp[q4];
                    wv[q4 * 2 + 0] = packh2(v.x, v.y);
                    wv[q4 * 2 + 1] = packh2(v.z, v.w);
                }
            } else {
                #pragma unroll
                for (int q4 = 0; q4 < 8; q4++) wv[q4] = 0u;
            }
            int blockbase = r * 64 + ((c * 8) ^ (rs & 24));
            int lo = rs & 4;
            *(uint4*)&xk[blockbase + lo]       = make_uint4(wv[0], wv[1], wv[2], wv[3]);
            *(uint4*)&xk[blockbase + (lo ^ 4)] = make_uint4(wv[4], wv[5], wv[6], wv[7]);
        }
        __syncthreads();

        // layer1: M=32, N=8 per warp (n = w*8+g), K=128
        float acc[2][4];
        {
            float p0 = qproj[w * 8 + 2 * tig], p1 = qproj[w * 8 + 2 * tig + 1];
            acc[0][0] = p0; acc[0][1] = p1; acc[0][2] = p0; acc[0][3] = p1;
            acc[1][0] = p0; acc[1][1] = p1; acc[1][2] = p0; acc[1][3] = p1;
        }
        int nb = (w * 8 + g) * 64;
        #pragma unroll
        for (int s = 0; s < 8; s++) {
            unsigned a[2][4], bb[2];
            int k0 = (s * 8 + tig) ^ gsw, k1 = (s * 8 + tig + 4) ^ gsw;
            #pragma unroll
            for (int mt = 0; mt < 2; mt++) {
                int r0 = mt * 16 + g;
                a[mt][0] = xk[r0 * 64 + k0];
                a[mt][1] = xk[(r0 + 8) * 64 + k0];
                a[mt][2] = xk[r0 * 64 + k1];
                a[mt][3] = xk[(r0 + 8) * 64 + k1];
            }
            bb[0] = WtB[nb + k0];
            bb[1] = WtB[nb + k1];
            mma_f16(acc[0], a[0], bb);
            mma_f16(acc[1], a[1], bb);
        }
        // dice -> h1s
        {
            int col = w * 8 + 2 * tig;
            float al0 = a1s[col], al1 = a1s[col + 1];
            #pragma unroll
            for (int mt = 0; mt < 2; mt++) {
                int r0 = mt * 16 + g;
                h1s[r0 * 68 + col]           = dicef(acc[mt][0], al0);
                h1s[r0 * 68 + col + 1]       = dicef(acc[mt][1], al1);
                h1s[(r0 + 8) * 68 + col]     = dicef(acc[mt][2], al0);
                h1s[(r0 + 8) * 68 + col + 1] = dicef(acc[mt][3], al1);
            }
        }
        __syncthreads();

        // layer2 + layer3 (SIMT): warp w handles rows w, w+8, w+16, w+24
        #pragma unroll
        for (int tt = 0; tt < 4; tt++) {
            int r = tt * 8 + w;
            int t = t0 + r;
            if (t < L) {
                float v = 0.0f;
                if (lane < 16) {
                    float accv = 0.0f;
                    #pragma unroll 4
                    for (int j = 0; j < 64; j++) accv += h1s[r * 68 + j] * W2s[j * 16 + lane];
                    v = dicef(accv, a2s[lane]) * W3s[lane];
                }
                #pragma unroll
                for (int off = 16; off > 0; off >>= 1) v += __shfl_xor_sync(0xffffffffu, v, off);
                if (lane == 0) g_att[(size_t)t * B + b] = sigmoidf_(v);
            }
        }
        __syncthreads();
    }
}

// ---------------- fused AUGRU scan: fp16 MMA, x-projection computed in-loop ----------------
// dynamic smem words: Wxu 0, Wxr 8192, Wxc 16384, Whu 24576, Whr 32768, Whc 40960,
//                     hT 49152, rhT 51200, xT[2] 53248/55296. total 57344 words = 229376 B
#define OFF_WXU 0
#define OFF_WXR 8192
#define OFF_WXC 16384
#define OFF_WHU 24576
#define OFF_WHR 32768
#define OFF_WHC 40960
#define OFF_HT  49152
#define OFF_RHT 51200
#define OFF_XT  53248

__global__ __launch_bounds__(256) void k_augru(
    const float* __restrict__ x, const int* __restrict__ slen,
    const float* __restrict__ Wu, const float* __restrict__ Wr, const float* __restrict__ Wc,
    float* __restrict__ out)
{
    extern __shared__ unsigned smw[];
    __shared__ int   Ls[32];
    __shared__ int   bis[32];
    __shared__ float atts[2][32];
    __shared__ int   LmaxS;

    int tid = threadIdx.x;

    if (tid < 32) {
        int b = g_perm[blockIdx.x * 32 + tid];
        bis[tid] = b;
        int L = slen[b]; L = min(max(L, 0), T);
        Ls[tid] = L;
    }
    for (int e = tid; e < 4096; e += 256) smw[OFF_HT + e] = 0u;   // hT + rhT
    __syncthreads();

    // weights -> fp16 B-layout [n=128][kw=64], swizzled
    {
        const float* srcs[6] = { Wu, Wr, Wc, Wu + 16384, Wr + 16384, Wc + 16384 };
        #pragma unroll
        for (int m = 0; m < 6; m++) {
            const float* S = srcs[m];
            unsigned* Wd = smw + m * 8192;
            for (int e = tid; e < 8192; e += 256) {
                int n = e & 127, kw = e >> 7;
                float v0 = S[(2 * kw) * 128 + n];
                float v1 = S[(2 * kw + 1) * 128 + n];
                Wd[n * 64 + (kw ^ ((n & 7) << 2))] = packh2(v0, v1);
            }
        }
    }
    if (tid == 0) { int m = 0; for (int i = 0; i < 32; i++) m = max(m, Ls[i]); LmaxS = m; }
    __syncthreads();
    const int Lmax = LmaxS;

    const int r_st = tid >> 3, c_st = tid & 7;        // staging: 8 threads per row
    const int rs_st = (r_st & 7) << 2;
    const size_t xrow = (size_t)bis[r_st] * T;

    // stage xT[0] for t=0, atts[0]
    {
        unsigned* dst = smw + OFF_XT;
        const float4* xp = (const float4*)&x[(xrow + 0) * D + c_st * 16];
        unsigned wv[8];
        #pragma unroll
        for (int q4 = 0; q4 < 4; q4++) {
            float4 v = xp[q4];
            wv[q4 * 2 + 0] = packh2(v.x, v.y);
            wv[q4 * 2 + 1] = packh2(v.z, v.w);
        }
        int blockbase = r_st * 64 + ((c_st * 8) ^ (rs_st & 24));
        int lo = rs_st & 4;
        *(uint4*)&dst[blockbase + lo]       = make_uint4(wv[0], wv[1], wv[2], wv[3]);
        *(uint4*)&dst[blockbase + (lo ^ 4)] = make_uint4(wv[4], wv[5], wv[6], wv[7]);
        if (tid < 32) atts[0][tid] = g_att[(size_t)0 * B + bis[tid]];
    }
    __syncthreads();

    const int w = tid >> 5, lane = tid & 31, g = lane >> 2, tig = lane & 3;
    const int gsw = g << 2;
    const int n0w = w * 16;

    int myL[4];
    float hm[2][2][4];
    #pragma unroll
    for (int ri = 0; ri < 4; ri++) myL[ri] = Ls[(ri >> 1) * 16 + (ri & 1) * 8 + g];
    #pragma unroll
    for (int mt = 0; mt < 2; mt++)
        #pragma unroll
        for (int nt = 0; nt < 2; nt++)
            #pragma unroll
            for (int k = 0; k < 4; k++) hm[mt][nt][k] = 0.0f;

    unsigned* hT  = smw + OFF_HT;
    unsigned* rhT = smw + OFF_RHT;

    for (int t = 0; t < Lmax; t++) {
        int cur = t & 1, nxt = cur ^ 1;
        unsigned* xTc = smw + OFF_XT + cur * 2048;
        unsigned* xTn = smw + OFF_XT + nxt * 2048;

        // 1. prefetch x and att for t+1
        int tn = min(t + 1, T - 1);
        float4 xa[4];
        {
            const float4* xp = (const float4*)&x[(xrow + tn) * D + c_st * 16];
            #pragma unroll
            for (int q4 = 0; q4 < 4; q4++) xa[q4] = xp[q4];
        }
        float attn_v = 0.0f;
        if (tid < 32) attn_v = g_att[(size_t)tn * B + bis[tid]];

        // 2. phase A: accU/accR (x+h GEMMs), accC (x GEMM)
        float accU[2][2][4], accR[2][2][4], accC[2][2][4];
        #pragma unroll
        for (int mt = 0; mt < 2; mt++)
            #pragma unroll
            for (int nt = 0; nt < 2; nt++)
                #pragma unroll
                for (int k = 0; k < 4; k++) { accU[mt][nt][k] = 0.0f; accR[mt][nt][k] = 0.0f; accC[mt][nt][k] = 0.0f; }

        #pragma unroll
        for (int s = 0; s < 8; s++) {
            int k0 = (s * 8 + tig) ^ gsw, k1 = (s * 8 + tig + 4) ^ gsw;
            unsigned ax[2][4], ah[2][4];
            #pragma unroll
            for (int mt = 0; mt < 2; mt++) {
                int r0 = mt * 16 + g;
                ax[mt][0] = xTc[r0 * 64 + k0];
                ax[mt][1] = xTc[(r0 + 8) * 64 + k0];
                ax[mt][2] = xTc[r0 * 64 + k1];
                ax[mt][3] = xTc[(r0 + 8) * 64 + k1];
                ah[mt][0] = hT[r0 * 64 + k0];
                ah[mt][1] = hT[(r0 + 8) * 64 + k0];
                ah[mt][2] = hT[r0 * 64 + k1];
                ah[mt][3] = hT[(r0 + 8) * 64 + k1];
            }
            #pragma unroll
            for (int nt = 0; nt < 2; nt++) {
                int nb = (n0w + nt * 8 + g) * 64;
                unsigned bxu[2], bhu[2], bxr[2], bhr[2], bxc[2];
                bxu[0] = smw[OFF_WXU + nb + k0]; bxu[1] = smw[OFF_WXU + nb + k1];
                bhu[0] = smw[OFF_WHU + nb + k0]; bhu[1] = smw[OFF_WHU + nb + k1];
                bxr[0] = smw[OFF_WXR + nb + k0]; bxr[1] = smw[OFF_WXR + nb + k1];
                bhr[0] = smw[OFF_WHR + nb + k0]; bhr[1] = smw[OFF_WHR + nb + k1];
                bxc[0] = smw[OFF_WXC + nb + k0]; bxc[1] = smw[OFF_WXC + nb + k1];
                #pragma unroll
                for (int mt = 0; mt < 2; mt++) {
                    mma_f16(accU[mt][nt], ax[mt], bxu);
                    mma_f16(accU[mt][nt], ah[mt], bhu);
                    mma_f16(accR[mt][nt], ax[mt], bxr);
                    mma_f16(accR[mt][nt], ah[mt], bhr);
                    mma_f16(accC[mt][nt], ax[mt], bxc);
                }
            }
        }

        // 3. store prefetched x into xT[nxt]; atts[nxt]
        {
            unsigned wv[8];
            #pragma unroll
            for (int q4 = 0; q4 < 4; q4++) {
                wv[q4 * 2 + 0] = packh2(xa[q4].x, xa[q4].y);
                wv[q4 * 2 + 1] = packh2(xa[q4].z, xa[q4].w);
            }
            int blockbase = r_st * 64 + ((c_st * 8) ^ (rs_st & 24));
            int lo = rs_st & 4;
            *(uint4*)&xTn[blockbase + lo]       = make_uint4(wv[0], wv[1], wv[2], wv[3]);
            *(uint4*)&xTn[blockbase + (lo ^ 4)] = make_uint4(wv[4], wv[5], wv[6], wv[7]);
            if (tid < 32) atts[nxt][tid] = attn_v;
        }

        // 4. gates, write r*h
        float uu[2][2][4];
        #pragma unroll
        for (int mt = 0; mt < 2; mt++)
            #pragma unroll
            for (int nt = 0; nt < 2; nt++) {
                int kwc = w * 8 + nt * 4 + tig;
                #pragma unroll
                for (int half = 0; half < 2; half++) {
                    int row = mt * 16 + half * 8 + g;
                    float u0 = sigmoidf_(accU[mt][nt][half * 2 + 0]);
                    float u1 = sigmoidf_(accU[mt][nt][half * 2 + 1]);
                    float r0 = sigmoidf_(accR[mt][nt][half * 2 + 0]);
                    float r1 = sigmoidf_(accR[mt][nt][half * 2 + 1]);
                    uu[mt][nt][half * 2 + 0] = u0;
                    uu[mt][nt][half * 2 + 1] = u1;
                    rhT[row * 64 + (kwc ^ gsw)] =
                        packh2(r0 * hm[mt][nt][half * 2 + 0], r1 * hm[mt][nt][half * 2 + 1]);
                }
            }
        __syncthreads();   // rhT ready

        // 6. phase B: accC += (r*h) @ Whc
        #pragma unroll
        for (int s = 0; s < 8; s++) {
            int k0 = (s * 8 + tig) ^ gsw, k1 = (s * 8 + tig + 4) ^ gsw;
            unsigned ar[2][4];
            #pragma unroll
            for (int mt = 0; mt < 2; mt++) {
                int r0 = mt * 16 + g;
                ar[mt][0] = rhT[r0 * 64 + k0];
                ar[mt][1] = rhT[(r0 + 8) * 64 + k0];
                ar[mt][2] = rhT[r0 * 64 + k1];
                ar[mt][3] = rhT[(r0 + 8) * 64 + k1];
            }
            #pragma unroll
            for (int nt = 0; nt < 2; nt++) {
                int nb = (n0w + nt * 8 + g) * 64;
                unsigned bc[2];
                bc[0] = smw[OFF_WHC + nb + k0];
                bc[1] = smw[OFF_WHC + nb + k1];
                #pragma unroll
                for (int mt = 0; mt < 2; mt++)
                    mma_f16(accC[mt][nt], ar[mt], bc);
            }
        }

        // 7. h update + refresh hT
        #pragma unroll
        for (int mt = 0; mt < 2; mt++)
            #pragma unroll
            for (int nt = 0; nt < 2; nt++) {
                int kwc = w * 8 + nt * 4 + tig;
                #pragma unroll
                for (int half = 0; half < 2; half++) {
                    int ri = mt * 2 + half;
                    int row = mt * 16 + half * 8 + g;
                    if (t < myL[ri]) {
                        float a_att = atts[cur][row];
                        float c0 = tanhf_(accC[mt][nt][half * 2 + 0]);
                        float c1 = tanhf_(accC[mt][nt][half * 2 + 1]);
                        float ut0 = uu[mt][nt][half * 2 + 0] * a_att;
                        float ut1 = uu[mt][nt][half * 2 + 1] * a_att;
                        hm[mt][nt][half * 2 + 0] += ut0 * (c0 - hm[mt][nt][half * 2 + 0]);
                        hm[mt][nt][half * 2 + 1] += ut1 * (c1 - hm[mt][nt][half * 2 + 1]);
                    }
                    hT[row * 64 + (kwc ^ gsw)] =
                        packh2(hm[mt][nt][half * 2 + 0], hm[mt][nt][half * 2 + 1]);
                }
            }
        __syncthreads();   // hT/rhT/xT/atts safe
    }

    // write final h
    #pragma unroll
    for (int mt = 0; mt < 2; mt++)
        #pragma unroll
        for (int nt = 0; nt < 2; nt++) {
            int col = n0w + nt * 8 + tig * 2;
            #pragma unroll
            for (int half = 0; half < 2; half++) {
                int row = mt * 16 + half * 8 + g;
                size_t base = (size_t)bis[row] * U + col;
                out[base]     = hm[mt][nt][half * 2 + 0];
                out[base + 1] = hm[mt][nt][half * 2 + 1];
            }
        }
}

// ---------------- launch ----------------
extern "C" void kernel_launch(void* const* d_in, const int* in_sizes, int n_in,
                              void* d_out, int out_size)
{
    const float* x    = (const float*)d_in[0];
    const float* q    = (const float*)d_in[1];
    const int*   slen = (const int*)d_in[2];
    const float* W1   = (const float*)d_in[3];
    const float* a1   = (const float*)d_in[4];
    const float* W2   = (const float*)d_in[5];
    const float* a2   = (const float*)d_in[6];
    const float* W3   = (const float*)d_in[7];
    const float* Wu   = (const float*)d_in[8];
    const float* Wr   = (const float*)d_in[9];
    const float* Wc   = (const float*)d_in[10];
    float* out = (float*)d_out;

    const int AUGRU_SMEM = 57344 * 4;   // 229376 B

    cudaFuncSetAttribute(k_augru, cudaFuncAttributeMaxDynamicSharedMemorySize, AUGRU_SMEM);

    k_sort<<<1, 512>>>(slen);
    k_att<<<B, 256>>>(x, q, slen, W1, a1, W2, a2, W3);
    k_augru<<<B / 32, 256, AUGRU_SMEM>>>(x, slen, Wu, Wr, Wc, out);
}

// round 4
// speedup vs baseline: 6.8472x; 1.0257x over previous
#include <cuda_runtime.h>
#include <cuda_fp16.h>
#include <math.h>

#define B 4096
#define T 200
#define D 128
#define U 128

// ---------------- device scratch ----------------
__device__ __align__(128) float g_att[(size_t)T * B];                  // [t][b]
__device__ __align__(128) unsigned g_xproj[(size_t)T * B * 192];       // [t][p][192] packed half2
__device__ int g_perm[B];

__device__ __forceinline__ float sigt(float x) {          // sigmoid, 1 MUFU
    float t;
    asm("tanh.approx.f32 %0, %1;" : "=f"(t) : "f"(0.5f * x));
    return fmaf(0.5f, t, 0.5f);
}
__device__ __forceinline__ float tanhp(float x) {          // precise tanh, 2 MUFU
    return 1.0f - 2.0f / (1.0f + __expf(2.0f * x));
}
__device__ __forceinline__ float dicef(float x, float alpha) {
    float p = sigt(x);
    return p * x + alpha * (1.0f - p) * x;
}
__device__ __forceinline__ unsigned packh2(float a, float b) {
    __half2 h = __floats2half2_rn(a, b);
    return *(unsigned*)&h;
}
__device__ __forceinline__ float2 unpackh2(unsigned u) {
    return __half22float2(*(__half2*)&u);
}
__device__ __forceinline__ void mma_f16(float c[4], const unsigned a[4], const unsigned b[2]) {
    asm("mma.sync.aligned.m16n8k16.row.col.f32.f16.f16.f32 "
        "{%0,%1,%2,%3}, {%4,%5,%6,%7}, {%8,%9}, {%0,%1,%2,%3};\n"
        : "+f"(c[0]), "+f"(c[1]), "+f"(c[2]), "+f"(c[3])
        : "r"(a[0]), "r"(a[1]), "r"(a[2]), "r"(a[3]), "r"(b[0]), "r"(b[1]));
}

// ---------------- counting sort ----------------
__global__ __launch_bounds__(512) void k_sort(const int* __restrict__ slen) {
    __shared__ int cnt[256];
    __shared__ int off[256];
    int tid = threadIdx.x;
    if (tid < 256) cnt[tid] = 0;
    __syncthreads();
    for (int b = tid; b < B; b += 512) {
        int L = slen[b]; L = min(max(L, 0), T);
        atomicAdd(&cnt[L], 1);
    }
    __syncthreads();
    if (tid == 0) {
        int acc = 0;
        for (int i = 0; i <= T; i++) { off[i] = acc; acc += cnt[i]; }
    }
    __syncthreads();
    for (int b = tid; b < B; b += 512) {
        int L = slen[b]; L = min(max(L, 0), T);
        int pos = atomicAdd(&off[L], 1);
        g_perm[pos] = b;
    }
}

// ---------------- attention: one block per batch row ----------------
__global__ __launch_bounds__(256) void k_att(
    const float* __restrict__ x, const float* __restrict__ q_all,
    const int* __restrict__ slen,
    const float* __restrict__ W1, const float* __restrict__ a1,
    const float* __restrict__ W2, const float* __restrict__ a2,
    const float* __restrict__ W3)
{
    __shared__ unsigned WtB[64 * 64];
    __shared__ unsigned xk[32 * 64];
    __shared__ float h1s[32 * 68];
    __shared__ float W2s[64 * 16];
    __shared__ float qs[D];
    __shared__ float qproj[64];
    __shared__ float a1s[64];
    __shared__ float a2s[16];
    __shared__ float W3s[16];

    int b = blockIdx.x;
    int tid = threadIdx.x;
    int L = slen[b]; L = min(max(L, 0), T);

    if (tid < D) qs[tid] = q_all[(size_t)b * D + tid];
    if (tid < 64) a1s[tid] = a1[tid];
    if (tid < 16) { a2s[tid] = a2[tid]; W3s[tid] = W3[tid]; }
    for (int e = tid; e < 64 * 16; e += 256) W2s[e] = W2[e];
    __syncthreads();

    for (int e = tid; e < 64 * 64; e += 256) {
        int n = e & 63, kw = e >> 6;
        int d0 = 2 * kw, d1 = 2 * kw + 1;
        float v0 = W1[(128 + d0) * 64 + n] - W1[(256 + d0) * 64 + n] + qs[d0] * W1[(384 + d0) * 64 + n];
        float v1 = W1[(128 + d1) * 64 + n] - W1[(256 + d1) * 64 + n] + qs[d1] * W1[(384 + d1) * 64 + n];
        WtB[n * 64 + (kw ^ ((n & 7) << 2))] = packh2(v0, v1);
    }
    if (tid < 64) {
        float acc = 0.0f;
        for (int d = 0; d < D; d++)
            acc += qs[d] * (W1[d * 64 + tid] + W1[(256 + d) * 64 + tid]);
        qproj[tid] = acc;
    }
    __syncthreads();
    if (L == 0) return;

    const int w = tid >> 5, lane = tid & 31, g = lane >> 2, tig = lane & 3;
    const int gsw = g << 2;

    for (int t0 = 0; t0 < L; t0 += 32) {
        {
            int r = tid >> 3, c = tid & 7;
            int rs = (r & 7) << 2;
            int t = t0 + r;
            unsigned wv[8];
            if (t < L) {
                const float4* xp = (const float4*)&x[((size_t)b * T + t) * D + c * 16];
                #pragma unroll
                for (int q4 = 0; q4 < 4; q4++) {
                    float4 v = xp[q4];
                    wv[q4 * 2 + 0] = packh2(v.x, v.y);
                    wv[q4 * 2 + 1] = packh2(v.z, v.w);
                }
            } else {
                #pragma unroll
                for (int q4 = 0; q4 < 8; q4++) wv[q4] = 0u;
            }
            int blockbase = r * 64 + ((c * 8) ^ (rs & 24));
            int lo = rs & 4;
            *(uint4*)&xk[blockbase + lo]       = make_uint4(wv[0], wv[1], wv[2], wv[3]);
            *(uint4*)&xk[blockbase + (lo ^ 4)] = make_uint4(wv[4], wv[5], wv[6], wv[7]);
        }
        __syncthreads();

        float acc[2][4];
        {
            float p0 = qproj[w * 8 + 2 * tig], p1 = qproj[w * 8 + 2 * tig + 1];
            acc[0][0] = p0; acc[0][1] = p1; acc[0][2] = p0; acc[0][3] = p1;
            acc[1][0] = p0; acc[1][1] = p1; acc[1][2] = p0; acc[1][3] = p1;
        }
        int nb = (w * 8 + g) * 64;
        #pragma unroll
        for (int s = 0; s < 8; s++) {
            unsigned a[2][4], bb[2];
            int k0 = (s * 8 + tig) ^ gsw, k1 = (s * 8 + tig + 4) ^ gsw;
            #pragma unroll
            for (int mt = 0; mt < 2; mt++) {
                int r0 = mt * 16 + g;
                a[mt][0] = xk[r0 * 64 + k0];
                a[mt][1] = xk[(r0 + 8) * 64 + k0];
                a[mt][2] = xk[r0 * 64 + k1];
                a[mt][3] = xk[(r0 + 8) * 64 + k1];
            }
            bb[0] = WtB[nb + k0];
            bb[1] = WtB[nb + k1];
            mma_f16(acc[0], a[0], bb);
            mma_f16(acc[1], a[1], bb);
        }
        {
            int col = w * 8 + 2 * tig;
            float al0 = a1s[col], al1 = a1s[col + 1];
            #pragma unroll
            for (int mt = 0; mt < 2; mt++) {
                int r0 = mt * 16 + g;
                h1s[r0 * 68 + col]           = dicef(acc[mt][0], al0);
                h1s[r0 * 68 + col + 1]       = dicef(acc[mt][1], al1);
                h1s[(r0 + 8) * 68 + col]     = dicef(acc[mt][2], al0);
                h1s[(r0 + 8) * 68 + col + 1] = dicef(acc[mt][3], al1);
            }
        }
        __syncthreads();

        #pragma unroll
        for (int tt = 0; tt < 4; tt++) {
            int r = tt * 8 + w;
            int t = t0 + r;
            if (t < L) {
                float v = 0.0f;
                if (lane < 16) {
                    float accv = 0.0f;
                    #pragma unroll 4
                    for (int j = 0; j < 64; j++) accv += h1s[r * 68 + j] * W2s[j * 16 + lane];
                    v = dicef(accv, a2s[lane]) * W3s[lane];
                }
                #pragma unroll
                for (int off = 16; off > 0; off >>= 1) v += __shfl_xor_sync(0xffffffffu, v, off);
                if (lane == 0) g_att[(size_t)t * B + b] = sigt(v);
            }
        }
        __syncthreads();
    }
}

// ---------------- x projections: weights in regs, sorted fp16 output ----------------
// grid 512; block i handles sorted positions p = i + 512*j, j=0..7
__global__ __launch_bounds__(256) void k_xproj(
    const float* __restrict__ x, const int* __restrict__ slen,
    const float* __restrict__ Wu, const float* __restrict__ Wr, const float* __restrict__ Wc)
{
    extern __shared__ unsigned smw[];   // 24576 words: stage weights, then reuse (xk @0, xout @2048)
    int tid = threadIdx.x;

    {
        const float* srcs[3] = { Wu, Wr, Wc };
        #pragma unroll
        for (int m = 0; m < 3; m++) {
            const float* S = srcs[m];
            unsigned* Wd = smw + m * 8192;
            for (int e = tid; e < 8192; e += 256) {
                int n = e & 127, kw = e >> 7;
                Wd[n * 64 + (kw ^ ((n & 7) << 2))] = packh2(S[(2 * kw) * 128 + n], S[(2 * kw + 1) * 128 + n]);
            }
        }
    }
    __syncthreads();

    const int w = tid >> 5, lane = tid & 31, g = lane >> 2, tig = lane & 3;
    const int gsw = g << 2;

    // hoist B-fragments: warp w -> cols w*48 .. w*48+47 (6 n-tiles across the 3 gates)
    unsigned wb[6][8][2];
    #pragma unroll
    for (int nt = 0; nt < 6; nt++) {
        int col = w * 48 + nt * 8 + g;       // 0..383
        int nb = (col >> 7) * 8192 + (col & 127) * 64;
        #pragma unroll
        for (int s = 0; s < 8; s++) {
            int k0 = (s * 8 + tig) ^ gsw, k1 = (s * 8 + tig + 4) ^ gsw;
            wb[nt][s][0] = smw[nb + k0];
            wb[nt][s][1] = smw[nb + k1];
        }
    }
    __syncthreads();   // staging region now reusable

    unsigned* xk   = smw;           // 2048 words
    unsigned* xout = smw + 2048;    // 32*196 words

    for (int j = 0; j < 8; j++) {
        int p = blockIdx.x + j * 512;
        int b = g_perm[p];
        int L = slen[b]; L = min(max(L, 0), T);
        if (L == 0) continue;

        for (int t0 = 0; t0 < L; t0 += 32) {
            {
                int r = tid >> 3, c = tid & 7;
                int rs = (r & 7) << 2;
                int t = t0 + r;
                if (t < L) {
                    const float4* xp = (const float4*)&x[((size_t)b * T + t) * D + c * 16];
                    unsigned wv[8];
                    #pragma unroll
                    for (int q4 = 0; q4 < 4; q4++) {
                        float4 v = xp[q4];
                        wv[q4 * 2 + 0] = packh2(v.x, v.y);
                        wv[q4 * 2 + 1] = packh2(v.z, v.w);
                    }
                    int blockbase = r * 64 + ((c * 8) ^ (rs & 24));
                    int lo = rs & 4;
                    *(uint4*)&xk[blockbase + lo]       = make_uint4(wv[0], wv[1], wv[2], wv[3]);
                    *(uint4*)&xk[blockbase + (lo ^ 4)] = make_uint4(wv[4], wv[5], wv[6], wv[7]);
                }
            }
            __syncthreads();

            float acc[2][6][4];
            #pragma unroll
            for (int mt = 0; mt < 2; mt++)
                #pragma unroll
                for (int nt = 0; nt < 6; nt++)
                    #pragma unroll
                    for (int k = 0; k < 4; k++) acc[mt][nt][k] = 0.0f;

            #pragma unroll
            for (int s = 0; s < 8; s++) {
                int k0 = (s * 8 + tig) ^ gsw, k1 = (s * 8 + tig + 4) ^ gsw;
                unsigned a[2][4];
                #pragma unroll
                for (int mt = 0; mt < 2; mt++) {
                    int r0 = mt * 16 + g;
                    a[mt][0] = xk[r0 * 64 + k0];
                    a[mt][1] = xk[(r0 + 8) * 64 + k0];
                    a[mt][2] = xk[r0 * 64 + k1];
                    a[mt][3] = xk[(r0 + 8) * 64 + k1];
                }
                #pragma unroll
                for (int nt = 0; nt < 6; nt++) {
                    mma_f16(acc[0][nt], a[0], wb[nt][s]);
                    mma_f16(acc[1][nt], a[1], wb[nt][s]);
                }
            }

            // c-frags -> xout [trow][196] (packed col pairs, c2 = col/2)
            #pragma unroll
            for (int mt = 0; mt < 2; mt++)
                #pragma unroll
                for (int nt = 0; nt < 6; nt++) {
                    int c2 = w * 24 + nt * 4 + tig;
                    xout[(mt * 16 + g) * 196 + c2]     = packh2(acc[mt][nt][0], acc[mt][nt][1]);
                    xout[(mt * 16 + 8 + g) * 196 + c2] = packh2(acc[mt][nt][2], acc[mt][nt][3]);
                }
            __syncthreads();

            {
                int r = tid >> 3, c = tid & 7;
                int t = t0 + r;
                if (t < L) {
                    size_t gb = ((size_t)t * B + p) * 192;
                    #pragma unroll
                    for (int q4 = 0; q4 < 6; q4++) {
                        uint4 v = *(uint4*)&xout[r * 196 + c * 4 + q4 * 32];
                        *(uint4*)&g_xproj[gb + c * 4 + q4 * 32] = v;
                    }
                }
            }
            __syncthreads();
        }
    }
}

// ---------------- AUGRU scan: weights in regs, xproj streamed from global ----------------
// smem words: Whu 0, Whr 8192, Whc 16384 (staging, idle after reg-load), hT 24576, rhT 26624
__global__ __launch_bounds__(256) void k_augru(
    const int* __restrict__ slen,
    const float* __restrict__ Wu, const float* __restrict__ Wr, const float* __restrict__ Wc,
    float* __restrict__ out)
{
    extern __shared__ unsigned smw[];
    unsigned* hT  = smw + 24576;
    unsigned* rhT = smw + 26624;
    __shared__ int   Ls[32];
    __shared__ int   bis[32];
    __shared__ float atts[32];
    __shared__ int   LmaxS;

    int tid = threadIdx.x;

    for (int e = tid; e < 8192; e += 256) {
        int n = e & 127, kw = e >> 7;
        int sw = n * 64 + (kw ^ ((n & 7) << 2));
        smw[sw]         = packh2(Wu[16384 + (2 * kw) * 128 + n], Wu[16384 + (2 * kw + 1) * 128 + n]);
        smw[8192 + sw]  = packh2(Wr[16384 + (2 * kw) * 128 + n], Wr[16384 + (2 * kw + 1) * 128 + n]);
        smw[16384 + sw] = packh2(Wc[16384 + (2 * kw) * 128 + n], Wc[16384 + (2 * kw + 1) * 128 + n]);
    }
    for (int e = tid; e < 4096; e += 256) hT[e] = 0u;   // hT + rhT
    if (tid < 32) {
        int b = g_perm[blockIdx.x * 32 + tid];
        bis[tid] = b;
        int L = slen[b]; L = min(max(L, 0), T);
        Ls[tid] = L;
    }
    __syncthreads();
    if (tid == 0) { int m = 0; for (int i = 0; i < 32; i++) m = max(m, Ls[i]); LmaxS = m; }

    const int w = tid >> 5, lane = tid & 31, g = lane >> 2, tig = lane & 3;
    const int gsw = g << 2;
    const int n0w = w * 16;

    // hoist recurrent-weight B-fragments into registers
    unsigned wu[2][8][2], wr[2][8][2], wc[2][8][2];
    #pragma unroll
    for (int nt = 0; nt < 2; nt++) {
        int nb = (n0w + nt * 8 + g) * 64;
        #pragma unroll
        for (int s = 0; s < 8; s++) {
            int k0 = (s * 8 + tig) ^ gsw, k1 = (s * 8 + tig + 4) ^ gsw;
            wu[nt][s][0] = smw[nb + k0];          wu[nt][s][1] = smw[nb + k1];
            wr[nt][s][0] = smw[8192 + nb + k0];   wr[nt][s][1] = smw[8192 + nb + k1];
            wc[nt][s][0] = smw[16384 + nb + k0];  wc[nt][s][1] = smw[16384 + nb + k1];
        }
    }
    __syncthreads();
    const int Lmax = LmaxS;
    const int p0 = blockIdx.x * 32;

    int myL[4];
    #pragma unroll
    for (int ri = 0; ri < 4; ri++) myL[ri] = Ls[(ri >> 1) * 16 + (ri & 1) * 8 + g];

    float hm[2][2][4];
    #pragma unroll
    for (int mt = 0; mt < 2; mt++)
        #pragma unroll
        for (int nt = 0; nt < 2; nt++)
            #pragma unroll
            for (int k = 0; k < 4; k++) hm[mt][nt][k] = 0.0f;

    for (int t = 0; t < Lmax; t++) {
        // issue xproj loads for THIS step (consumed after phase A -> latency hidden)
        unsigned xpf[2][2][2][3];
        {
            size_t tb = (size_t)t * B + p0;
            #pragma unroll
            for (int mt = 0; mt < 2; mt++)
                #pragma unroll
                for (int half = 0; half < 2; half++) {
                    size_t rb = (tb + mt * 16 + half * 8 + g) * 192 + w * 8 + tig;
                    #pragma unroll
                    for (int nt = 0; nt < 2; nt++)
                        #pragma unroll
                        for (int gate = 0; gate < 3; gate++)
                            xpf[mt][half][nt][gate] = g_xproj[rb + gate * 64 + nt * 4];
                }
        }
        if (tid < 32) atts[tid] = g_att[(size_t)t * B + bis[tid]];

        // phase A: accU = h@Whu, accR = h@Whr
        float accU[2][2][4], accR[2][2][4];
        #pragma unroll
        for (int mt = 0; mt < 2; mt++)
            #pragma unroll
            for (int nt = 0; nt < 2; nt++)
                #pragma unroll
                for (int k = 0; k < 4; k++) { accU[mt][nt][k] = 0.0f; accR[mt][nt][k] = 0.0f; }

        #pragma unroll
        for (int s = 0; s < 8; s++) {
            int k0 = (s * 8 + tig) ^ gsw, k1 = (s * 8 + tig + 4) ^ gsw;
            unsigned ah[2][4];
            #pragma unroll
            for (int mt = 0; mt < 2; mt++) {
                int r0 = mt * 16 + g;
                ah[mt][0] = hT[r0 * 64 + k0];
                ah[mt][1] = hT[(r0 + 8) * 64 + k0];
                ah[mt][2] = hT[r0 * 64 + k1];
                ah[mt][3] = hT[(r0 + 8) * 64 + k1];
            }
            #pragma unroll
            for (int nt = 0; nt < 2; nt++)
                #pragma unroll
                for (int mt = 0; mt < 2; mt++) {
                    mma_f16(accU[mt][nt], ah[mt], wu[nt][s]);
                    mma_f16(accR[mt][nt], ah[mt], wr[nt][s]);
                }
        }

        // gates u, r; write r*h
        float uu[2][2][4];
        #pragma unroll
        for (int mt = 0; mt < 2; mt++)
            #pragma unroll
            for (int nt = 0; nt < 2; nt++) {
                int kwc = w * 8 + nt * 4 + tig;
                #pragma unroll
                for (int half = 0; half < 2; half++) {
                    int row = mt * 16 + half * 8 + g;
                    float2 xu = unpackh2(xpf[mt][half][nt][0]);
                    float2 xr = unpackh2(xpf[mt][half][nt][1]);
                    float u0 = sigt(accU[mt][nt][half * 2 + 0] + xu.x);
                    float u1 = sigt(accU[mt][nt][half * 2 + 1] + xu.y);
                    float r0 = sigt(accR[mt][nt][half * 2 + 0] + xr.x);
                    float r1 = sigt(accR[mt][nt][half * 2 + 1] + xr.y);
                    uu[mt][nt][half * 2 + 0] = u0;
                    uu[mt][nt][half * 2 + 1] = u1;
                    rhT[row * 64 + (kwc ^ gsw)] =
                        packh2(r0 * hm[mt][nt][half * 2 + 0], r1 * hm[mt][nt][half * 2 + 1]);
                }
            }
        __syncthreads();   // rhT ready, atts visible

        // phase B: accC = x@Wxc (preloaded) + (r*h)@Whc
        float accC[2][2][4];
        #pragma unroll
        for (int mt = 0; mt < 2; mt++)
            #pragma unroll
            for (int nt = 0; nt < 2; nt++)
                #pragma unroll
                for (int half = 0; half < 2; half++) {
                    float2 xc = unpackh2(xpf[mt][half][nt][2]);
                    accC[mt][nt][half * 2 + 0] = xc.x;
                    accC[mt][nt][half * 2 + 1] = xc.y;
                }

        #pragma unroll
        for (int s = 0; s < 8; s++) {
            int k0 = (s * 8 + tig) ^ gsw, k1 = (s * 8 + tig + 4) ^ gsw;
            unsigned ar[2][4];
            #pragma unroll
            for (int mt = 0; mt < 2; mt++) {
                int r0 = mt * 16 + g;
                ar[mt][0] = rhT[r0 * 64 + k0];
                ar[mt][1] = rhT[(r0 + 8) * 64 + k0];
                ar[mt][2] = rhT[r0 * 64 + k1];
                ar[mt][3] = rhT[(r0 + 8) * 64 + k1];
            }
            #pragma unroll
            for (int nt = 0; nt < 2; nt++)
                #pragma unroll
                for (int mt = 0; mt < 2; mt++)
                    mma_f16(accC[mt][nt], ar[mt], wc[nt][s]);
        }

        // h update
        #pragma unroll
        for (int mt = 0; mt < 2; mt++)
            #pragma unroll
            for (int nt = 0; nt < 2; nt++) {
                int kwc = w * 8 + nt * 4 + tig;
                #pragma unroll
                for (int half = 0; half < 2; half++) {
                    int ri = mt * 2 + half;
                    int row = mt * 16 + half * 8 + g;
                    if (t < myL[ri]) {
                        float a_att = atts[row];
                        float c0 = tanhp(accC[mt][nt][half * 2 + 0]);
                        float c1 = tanhp(accC[mt][nt][half * 2 + 1]);
                        float ut0 = uu[mt][nt][half * 2 + 0] * a_att;
                        float ut1 = uu[mt][nt][half * 2 + 1] * a_att;
                        hm[mt][nt][half * 2 + 0] += ut0 * (c0 - hm[mt][nt][half * 2 + 0]);
                        hm[mt][nt][half * 2 + 1] += ut1 * (c1 - hm[mt][nt][half * 2 + 1]);
                    }
                    hT[row * 64 + (kwc ^ gsw)] =
                        packh2(hm[mt][nt][half * 2 + 0], hm[mt][nt][half * 2 + 1]);
                }
            }
        __syncthreads();
    }

    #pragma unroll
    for (int mt = 0; mt < 2; mt++)
        #pragma unroll
        for (int nt = 0; nt < 2; nt++) {
            int col = n0w + nt * 8 + tig * 2;
            #pragma unroll
            for (int half = 0; half < 2; half++) {
                int row = mt * 16 + half * 8 + g;
                size_t base = (size_t)bis[row] * U + col;
                out[base]     = hm[mt][nt][half * 2 + 0];
                out[base + 1] = hm[mt][nt][half * 2 + 1];
            }
        }
}

// ---------------- launch ----------------
extern "C" void kernel_launch(void* const* d_in, const int* in_sizes, int n_in,
                              void* d_out, int out_size)
{
    const float* x    = (const float*)d_in[0];
    const float* q    = (const float*)d_in[1];
    const int*   slen = (const int*)d_in[2];
    const float* W1   = (const float*)d_in[3];
    const float* a1   = (const float*)d_in[4];
    const float* W2   = (const float*)d_in[5];
    const float* a2   = (const float*)d_in[6];
    const float* W3   = (const float*)d_in[7];
    const float* Wu   = (const float*)d_in[8];
    const float* Wr   = (const float*)d_in[9];
    const float* Wc   = (const float*)d_in[10];
    float* out = (float*)d_out;

    const int XPROJ_SMEM = 24576 * 4;   // 98,304 B
    const int AUGRU_SMEM = 28672 * 4;   // 114,688 B

    cudaFuncSetAttribute(k_xproj, cudaFuncAttributeMaxDynamicSharedMemorySize, XPROJ_SMEM);
    cudaFuncSetAttribute(k_augru, cudaFuncAttributeMaxDynamicSharedMemorySize, AUGRU_SMEM);

    k_att<<<B, 256>>>(x, q, slen, W1, a1, W2, a2, W3);
    k_sort<<<1, 512>>>(slen);
    k_xproj<<<512, 256, XPROJ_SMEM>>>(x, slen, Wu, Wr, Wc);
    k_augru<<<B / 32, 256, AUGRU_SMEM>>>(slen, Wu, Wr, Wc, out);
}